// round 1
// baseline (speedup 1.0000x reference)
#include <cuda_runtime.h>

#define NUM_H 16
#define SEQ_T 2048
#define DIM   1024
#define HD    64

// Scratch (allocation-free rule: __device__ globals)
__device__ float g_q[NUM_H][SEQ_T][HD];   // 8 MB, pre-scaled by 1/sqrt(hd)
__device__ float g_k[NUM_H][SEQ_T][HD];   // 8 MB
__device__ float g_v[NUM_H][SEQ_T][HD];   // 8 MB
__device__ float g_y[SEQ_T][DIM];         // 8 MB, [t][h*64+c]

// ---------------------------------------------------------------------------
// SGEMM: C[M,N] = A[M,K] @ B[K,N]. Tiles 128x128x8, 256 threads, 8x8 microtile.
// MODE 0: plain, write C.
// MODE 1: QKV epilogue scatter into g_q/g_k/g_v (q scaled by 0.125), C unused.
// MODE 2: A is g_y (Ap ignored), write C.
// ---------------------------------------------------------------------------
template<int MODE>
__global__ __launch_bounds__(256)
void sgemm_kernel(const float* __restrict__ Ap, const float* __restrict__ B,
                  float* __restrict__ C, int M, int N, int K)
{
    const float* A = (MODE == 2) ? &g_y[0][0] : Ap;
    __shared__ float As[8][128];   // A tile stored transposed
    __shared__ float Bs[8][128];
    const int tid = threadIdx.x;
    const int bm = blockIdx.y, bn = blockIdx.x;
    const int tr = tid >> 4, tc = tid & 15;          // 16x16 thread grid

    const int a_r = tid >> 1, a_c = (tid & 1) * 4;   // A: 128x8, one float4/thread
    const int b_r = tid >> 5, b_c = (tid & 31) * 4;  // B: 8x128, one float4/thread

    const float* Aptr = A + (size_t)(bm * 128 + a_r) * K + a_c;
    const float* Bptr = B + (size_t)b_r * N + bn * 128 + b_c;

    float acc[8][8] = {};
    for (int k0 = 0; k0 < K; k0 += 8) {
        float4 av = *(const float4*)(Aptr + k0);
        float4 bv = *(const float4*)(Bptr + (size_t)k0 * N);
        As[a_c + 0][a_r] = av.x;
        As[a_c + 1][a_r] = av.y;
        As[a_c + 2][a_r] = av.z;
        As[a_c + 3][a_r] = av.w;
        *(float4*)&Bs[b_r][b_c] = bv;
        __syncthreads();
        #pragma unroll
        for (int k = 0; k < 8; k++) {
            float ra[8], rb[8];
            *(float4*)&ra[0] = *(const float4*)&As[k][tr * 8];
            *(float4*)&ra[4] = *(const float4*)&As[k][tr * 8 + 4];
            *(float4*)&rb[0] = *(const float4*)&Bs[k][tc * 8];
            *(float4*)&rb[4] = *(const float4*)&Bs[k][tc * 8 + 4];
            #pragma unroll
            for (int i = 0; i < 8; i++)
                #pragma unroll
                for (int j = 0; j < 8; j++)
                    acc[i][j] = fmaf(ra[i], rb[j], acc[i][j]);
        }
        __syncthreads();
    }

    const int row0 = bm * 128 + tr * 8;
    const int col0 = bn * 128 + tc * 8;
    if (MODE != 1) {
        #pragma unroll
        for (int i = 0; i < 8; i++) {
            *(float4*)&C[(size_t)(row0 + i) * N + col0]     = *(float4*)&acc[i][0];
            *(float4*)&C[(size_t)(row0 + i) * N + col0 + 4] = *(float4*)&acc[i][4];
        }
    } else {
        // col groups of 4 never cross a 64-col head boundary (col0 % 8 == 0)
        #pragma unroll
        for (int jg = 0; jg < 8; jg += 4) {
            const int n = col0 + jg;
            const int which = n >> 10;              // 0=q, 1=k, 2=v
            const int h = (n >> 6) & (NUM_H - 1);
            const int c = n & (HD - 1);
            float* dst = (which == 0) ? &g_q[h][0][0]
                       : (which == 1) ? &g_k[h][0][0] : &g_v[h][0][0];
            const float s = (which == 0) ? 0.125f : 1.0f;  // 1/sqrt(64)
            #pragma unroll
            for (int i = 0; i < 8; i++) {
                float4 v4;
                v4.x = acc[i][jg + 0] * s;
                v4.y = acc[i][jg + 1] * s;
                v4.z = acc[i][jg + 2] * s;
                v4.w = acc[i][jg + 3] * s;
                *(float4*)&dst[(size_t)(row0 + i) * HD + c] = v4;
            }
        }
    }
}

// ---------------------------------------------------------------------------
// Flash attention (no mask): one CTA per (64-query tile, head).
// Streams 64-key tiles; online softmax; O accumulated in registers (4x4/thread).
// Smem: Qs[64][64] | KP[64][65] (K tile, reused as P tile) | Vs[64][64] | stats
// ---------------------------------------------------------------------------
#define FLASH_SMEM_FLOATS (64*64 + 64*65 + 64*64 + 192)
#define FLASH_SMEM_BYTES  (FLASH_SMEM_FLOATS * 4)

__global__ __launch_bounds__(256)
void flash_kernel()
{
    extern __shared__ float sm[];
    float* Qs  = sm;               // [64][64]
    float* KP  = Qs + 64 * 64;     // [64][65]  (pad 65: <=2-way conflicts on K reads)
    float* Vs  = KP + 64 * 65;     // [64][64]
    float* m_s = Vs + 64 * 64;     // [64]
    float* l_s = m_s + 64;         // [64]
    float* sc_s = l_s + 64;        // [64]

    const int h  = blockIdx.y;
    const int qb = blockIdx.x;
    const int tid = threadIdx.x;
    const int ty = tid >> 4, tx = tid & 15;

    const float* Qg = &g_q[h][qb * 64][0];
    #pragma unroll
    for (int it = 0; it < 16; it++) {
        int idx = it * 256 + tid;
        Qs[idx] = Qg[idx];
    }
    if (tid < 64) { m_s[tid] = -1e30f; l_s[tid] = 0.f; }
    float acc[4][4] = {};
    __syncthreads();

    for (int kb = 0; kb < SEQ_T / 64; kb++) {
        const float* Kg = &g_k[h][kb * 64][0];
        const float* Vg = &g_v[h][kb * 64][0];
        #pragma unroll
        for (int it = 0; it < 16; it++) {
            int idx = it * 256 + tid;
            int r = idx >> 6, c = idx & 63;
            KP[r * 65 + c] = Kg[idx];
            Vs[idx]        = Vg[idx];
        }
        __syncthreads();

        // S = Q @ K^T  (Q already scaled)
        float s[4][4] = {};
        #pragma unroll 8
        for (int k = 0; k < 64; k++) {
            float rq[4], rk[4];
            #pragma unroll
            for (int i = 0; i < 4; i++) rq[i] = Qs[(4 * ty + i) * 64 + k];
            #pragma unroll
            for (int j = 0; j < 4; j++) rk[j] = KP[(4 * tx + j) * 65 + k];
            #pragma unroll
            for (int i = 0; i < 4; i++)
                #pragma unroll
                for (int j = 0; j < 4; j++)
                    s[i][j] = fmaf(rq[i], rk[j], s[i][j]);
        }
        __syncthreads();   // everyone done reading K tile; KP becomes P tile

        #pragma unroll
        for (int i = 0; i < 4; i++)
            #pragma unroll
            for (int j = 0; j < 4; j++)
                KP[(4 * ty + i) * 65 + 4 * tx + j] = s[i][j];
        __syncthreads();

        // Online softmax: 4 threads per row, 16 cols each; shfl reduce in 4-lane groups
        {
            const int row = tid >> 2, seg = tid & 3;
            float* Pr = &KP[row * 65 + seg * 16];
            float mx = -1e30f;
            #pragma unroll
            for (int c = 0; c < 16; c++) mx = fmaxf(mx, Pr[c]);
            mx = fmaxf(mx, __shfl_xor_sync(0xffffffffu, mx, 1));
            mx = fmaxf(mx, __shfl_xor_sync(0xffffffffu, mx, 2));
            const float m_old = m_s[row];
            const float m_new = fmaxf(m_old, mx);
            float sum = 0.f;
            #pragma unroll
            for (int c = 0; c < 16; c++) {
                float p = __expf(Pr[c] - m_new);
                Pr[c] = p;
                sum += p;
            }
            sum += __shfl_xor_sync(0xffffffffu, sum, 1);
            sum += __shfl_xor_sync(0xffffffffu, sum, 2);
            if (seg == 0) {
                const float corr = __expf(m_old - m_new);
                l_s[row]  = l_s[row] * corr + sum;
                m_s[row]  = m_new;
                sc_s[row] = corr;
            }
        }
        __syncthreads();

        // Rescale accumulator, then O += P @ V
        float scl[4];
        #pragma unroll
        for (int i = 0; i < 4; i++) scl[i] = sc_s[4 * ty + i];
        #pragma unroll
        for (int i = 0; i < 4; i++)
            #pragma unroll
            for (int j = 0; j < 4; j++)
                acc[i][j] *= scl[i];

        #pragma unroll 8
        for (int n = 0; n < 64; n++) {
            float rp[4], rv[4];
            #pragma unroll
            for (int i = 0; i < 4; i++) rp[i] = KP[(4 * ty + i) * 65 + n];
            #pragma unroll
            for (int j = 0; j < 4; j++) rv[j] = Vs[n * 64 + 4 * tx + j];
            #pragma unroll
            for (int i = 0; i < 4; i++)
                #pragma unroll
                for (int j = 0; j < 4; j++)
                    acc[i][j] = fmaf(rp[i], rv[j], acc[i][j]);
        }
        __syncthreads();   // protect KP/Vs before next tile load
    }

    float inv[4];
    #pragma unroll
    for (int i = 0; i < 4; i++) inv[i] = 1.0f / l_s[4 * ty + i];
    #pragma unroll
    for (int i = 0; i < 4; i++) {
        const int t = qb * 64 + 4 * ty + i;
        float4 o;
        o.x = acc[i][0] * inv[i];
        o.y = acc[i][1] * inv[i];
        o.z = acc[i][2] * inv[i];
        o.w = acc[i][3] * inv[i];
        *(float4*)&g_y[t][h * 64 + 4 * tx] = o;
    }
}

extern "C" void kernel_launch(void* const* d_in, const int* in_sizes, int n_in,
                              void* d_out, int out_size)
{
    (void)in_sizes; (void)n_in; (void)out_size;
    const float* x     = (const float*)d_in[0];
    const float* Wqkv  = (const float*)d_in[1];
    const float* Wproj = (const float*)d_in[2];
    float* out = (float*)d_out;

    // 49 KB dynamic smem > 48 KB default; idempotent, graph-capture-safe
    cudaFuncSetAttribute(flash_kernel,
                         cudaFuncAttributeMaxDynamicSharedMemorySize,
                         FLASH_SMEM_BYTES);

    // 1) QKV = x @ W_qkv, scattered per-head (q pre-scaled)
    sgemm_kernel<1><<<dim3(3 * DIM / 128, SEQ_T / 128), 256>>>(
        x, Wqkv, nullptr, SEQ_T, 3 * DIM, DIM);

    // 2) fused attention -> g_y [T, D]
    flash_kernel<<<dim3(SEQ_T / 64, NUM_H), 256, FLASH_SMEM_BYTES>>>();

    // 3) out = g_y @ W_proj
    sgemm_kernel<2><<<dim3(DIM / 128, SEQ_T / 128), 256>>>(
        nullptr, Wproj, out, SEQ_T, DIM, DIM);
}

// round 5
// speedup vs baseline: 1.3346x; 1.3346x over previous
#include <cuda_runtime.h>
#include <cuda_bf16.h>
#include <cstdint>

#define NUM_H 16
#define SEQ_T 2048
#define DIM   1024
#define HD    64

// ---------------- scratch (__device__ globals) -----------------------------
__device__ float g_q[NUM_H][SEQ_T][HD];   // pre-scaled by 1/8
__device__ float g_k[NUM_H][SEQ_T][HD];
__device__ float g_v[NUM_H][SEQ_T][HD];
__device__ float g_y[SEQ_T][DIM];

__device__ __align__(16) __nv_bfloat16 gA_hi[SEQ_T][DIM];
__device__ __align__(16) __nv_bfloat16 gA_lo[SEQ_T][DIM];
__device__ __align__(16) __nv_bfloat16 gBq_hi[3 * DIM][DIM];   // [N][K]
__device__ __align__(16) __nv_bfloat16 gBq_lo[3 * DIM][DIM];
__device__ __align__(16) __nv_bfloat16 gBp_hi[DIM][DIM];
__device__ __align__(16) __nv_bfloat16 gBp_lo[DIM][DIM];
__device__ __align__(16) __nv_bfloat16 gY_hi[SEQ_T][DIM];
__device__ __align__(16) __nv_bfloat16 gY_lo[SEQ_T][DIM];

// ---------------- PTX helpers (sm_80+ family-portable only) ----------------
__device__ __forceinline__ uint32_t smem_u32(const void* p) {
    uint32_t a;
    asm("{ .reg .u64 t; cvta.to.shared.u64 t, %1; cvt.u32.u64 %0, t; }" : "=r"(a) : "l"(p));
    return a;
}
#define CP_ASYNC16(dst, src) \
    asm volatile("cp.async.cg.shared.global [%0], [%1], 16;" :: "r"(dst), "l"(src))
#define CP_COMMIT() asm volatile("cp.async.commit_group;" ::: "memory")
#define CP_WAIT(n)  asm volatile("cp.async.wait_group %0;" :: "n"(n) : "memory")

__device__ __forceinline__ void ldsm4(uint32_t* r, uint32_t addr) {
    asm volatile("ldmatrix.sync.aligned.m8n8.x4.shared.b16 {%0,%1,%2,%3}, [%4];"
        : "=r"(r[0]), "=r"(r[1]), "=r"(r[2]), "=r"(r[3]) : "r"(addr));
}
__device__ __forceinline__ void mma16816(float* d, const uint32_t* a,
                                         uint32_t b0, uint32_t b1) {
    asm volatile("mma.sync.aligned.m16n8k16.row.col.f32.bf16.bf16.f32 "
        "{%0,%1,%2,%3}, {%4,%5,%6,%7}, {%8,%9}, {%0,%1,%2,%3};"
        : "+f"(d[0]), "+f"(d[1]), "+f"(d[2]), "+f"(d[3])
        : "r"(a[0]), "r"(a[1]), "r"(a[2]), "r"(a[3]), "r"(b0), "r"(b1));
}

// ---------------- convert kernels ------------------------------------------
template<int MODE>   // 0: x -> gA ; 1: g_y -> gY
__global__ void conv_split_kernel(const float* __restrict__ srcp)
{
    const float* src = (MODE == 1) ? &g_y[0][0] : srcp;
    __nv_bfloat16* hi = (MODE == 1) ? &gY_hi[0][0] : &gA_hi[0][0];
    __nv_bfloat16* lo = (MODE == 1) ? &gY_lo[0][0] : &gA_lo[0][0];
    int i = (blockIdx.x * blockDim.x + threadIdx.x) * 4;
    float4 v = *(const float4*)(src + i);
    __nv_bfloat16 h0 = __float2bfloat16(v.x), h1 = __float2bfloat16(v.y);
    __nv_bfloat16 h2 = __float2bfloat16(v.z), h3 = __float2bfloat16(v.w);
    __nv_bfloat16 l0 = __float2bfloat16(v.x - __bfloat162float(h0));
    __nv_bfloat16 l1 = __float2bfloat16(v.y - __bfloat162float(h1));
    __nv_bfloat16 l2 = __float2bfloat16(v.z - __bfloat162float(h2));
    __nv_bfloat16 l3 = __float2bfloat16(v.w - __bfloat162float(h3));
    *(__nv_bfloat162*)(hi + i)     = __nv_bfloat162(h0, h1);
    *(__nv_bfloat162*)(hi + i + 2) = __nv_bfloat162(h2, h3);
    *(__nv_bfloat162*)(lo + i)     = __nv_bfloat162(l0, l1);
    *(__nv_bfloat162*)(lo + i + 2) = __nv_bfloat162(l2, l3);
}

template<int MODE>   // W[K][N] -> out[N][K] hi/lo.  0: W_qkv ; 1: W_proj
__global__ void transpose_split_kernel(const float* __restrict__ W)
{
    const int N = (MODE == 0) ? 3 * DIM : DIM;
    __nv_bfloat16* hi = (MODE == 0) ? &gBq_hi[0][0] : &gBp_hi[0][0];
    __nv_bfloat16* lo = (MODE == 0) ? &gBq_lo[0][0] : &gBp_lo[0][0];
    __shared__ float t[32][33];
    const int n0 = blockIdx.x * 32, k0 = blockIdx.y * 32;
    const int tx = threadIdx.x, ty = threadIdx.y;
    #pragma unroll
    for (int i = ty; i < 32; i += 8)
        t[i][tx] = W[(size_t)(k0 + i) * N + n0 + tx];
    __syncthreads();
    #pragma unroll
    for (int i = ty; i < 32; i += 8) {
        float v = t[tx][i];
        __nv_bfloat16 h = __float2bfloat16(v);
        __nv_bfloat16 l = __float2bfloat16(v - __bfloat162float(h));
        hi[(size_t)(n0 + i) * DIM + k0 + tx] = h;
        lo[(size_t)(n0 + i) * DIM + k0 + tx] = l;
    }
}

// ---------------- warp-mma bf16 3-split GEMM -------------------------------
// D[128,128] tile; A [M][K] row-major, B [N][K] row-major (= col-major k x n)
// MODE 0: A=gA,B=gBq, scatter into g_q/g_k/g_v (q*0.125). MODE 1: A=gY,B=gBp -> C.
#define KCHUNK   32
#define RSTRIDE  40                      // halves per smem row (80 B, conflict-free)
#define TILE_B   (128 * RSTRIDE * 2)     // 10240 B per operand tile
#define STAGE_B  (4 * TILE_B)            // Ah|Al|Bh|Bl
#define GEMM_SMEM (2 * STAGE_B)          // 81920 B

template<int MODE>
__global__ __launch_bounds__(256)
void mma_gemm_kernel(float* __restrict__ C, int N)
{
    extern __shared__ char smem[];
    const uint32_t sb = smem_u32(smem);
    const int tid = threadIdx.x;
    const int bm = blockIdx.y, bn = blockIdx.x;
    const int w = tid >> 5, lane = tid & 31;
    const int wm = w >> 1, wn = w & 1;            // 4 x 2 warp grid
    const int lrow = lane & 15, lcol8 = (lane >> 4) * 8;
    const int gid = lane >> 2, tig = lane & 3;

    const __nv_bfloat16* Ahi = (MODE == 0) ? &gA_hi[0][0] : &gY_hi[0][0];
    const __nv_bfloat16* Alo = (MODE == 0) ? &gA_lo[0][0] : &gY_lo[0][0];
    const __nv_bfloat16* Bhi = (MODE == 0) ? &gBq_hi[0][0] : &gBp_hi[0][0];
    const __nv_bfloat16* Blo = (MODE == 0) ? &gBq_lo[0][0] : &gBp_lo[0][0];
    const __nv_bfloat16* srcs[4] = { Ahi, Alo, Bhi, Blo };

    // per-thread copy slots: 8 x (tile, row, seg)
    int cp_tile[8], cp_row[8], cp_seg[8];
    #pragma unroll
    for (int it = 0; it < 8; ++it) {
        int idx = it * 256 + tid;
        cp_tile[it] = idx >> 9;
        cp_row[it]  = (idx & 511) >> 2;
        cp_seg[it]  = idx & 3;
    }

    auto issue_load = [&](int c) {
        const uint32_t st = sb + (uint32_t)(c & 1) * STAGE_B;
        const int k0 = c * KCHUNK;
        #pragma unroll
        for (int it = 0; it < 8; ++it) {
            const int t = cp_tile[it];
            const int rbase = ((t < 2) ? bm : bn) * 128;
            const __nv_bfloat16* src = srcs[t]
                + (size_t)(rbase + cp_row[it]) * DIM + k0 + cp_seg[it] * 8;
            const uint32_t dst = st + t * TILE_B + cp_row[it] * (RSTRIDE * 2)
                               + cp_seg[it] * 16;
            CP_ASYNC16(dst, src);
        }
        CP_COMMIT();
    };

    float acc[2][8][4] = {};

    issue_load(0);
    const int NCHUNK = DIM / KCHUNK;      // 32
    for (int c = 0; c < NCHUNK; ++c) {
        if (c + 1 < NCHUNK) { issue_load(c + 1); CP_WAIT(1); }
        else                { CP_WAIT(0); }
        __syncthreads();

        const uint32_t st = sb + (uint32_t)(c & 1) * STAGE_B;
        const uint32_t aH = st, aL = st + TILE_B, bH = st + 2 * TILE_B, bL = st + 3 * TILE_B;

        #pragma unroll
        for (int kk = 0; kk < 2; ++kk) {
            const uint32_t koff = (kk * 16 + lcol8) * 2;
            uint32_t ah[2][4], al[2][4], bh[4][4], bl[4][4];
            #pragma unroll
            for (int mi = 0; mi < 2; ++mi) {
                const uint32_t ro = (wm * 32 + mi * 16 + lrow) * (RSTRIDE * 2) + koff;
                ldsm4(ah[mi], aH + ro);
                ldsm4(al[mi], aL + ro);
            }
            #pragma unroll
            for (int nq = 0; nq < 4; ++nq) {
                const uint32_t ro = (wn * 64 + nq * 16 + lrow) * (RSTRIDE * 2) + koff;
                ldsm4(bh[nq], bH + ro);
                ldsm4(bl[nq], bL + ro);
            }
            #pragma unroll
            for (int mi = 0; mi < 2; ++mi)
                #pragma unroll
                for (int nq = 0; nq < 4; ++nq) {
                    mma16816(acc[mi][nq * 2 + 0], ah[mi], bh[nq][0], bh[nq][2]);
                    mma16816(acc[mi][nq * 2 + 1], ah[mi], bh[nq][1], bh[nq][3]);
                    mma16816(acc[mi][nq * 2 + 0], ah[mi], bl[nq][0], bl[nq][2]);
                    mma16816(acc[mi][nq * 2 + 1], ah[mi], bl[nq][1], bl[nq][3]);
                    mma16816(acc[mi][nq * 2 + 0], al[mi], bh[nq][0], bh[nq][2]);
                    mma16816(acc[mi][nq * 2 + 1], al[mi], bh[nq][1], bh[nq][3]);
                }
        }
        __syncthreads();
    }

    // epilogue
    #pragma unroll
    for (int mi = 0; mi < 2; ++mi)
        #pragma unroll
        for (int nj = 0; nj < 8; ++nj) {
            const int row = bm * 128 + wm * 32 + mi * 16 + gid;
            const int n = bn * 128 + wn * 64 + nj * 8 + tig * 2;
            if (MODE == 0) {
                const int which = n >> 10;
                const int h = (n >> 6) & (NUM_H - 1);
                const int cc = n & (HD - 1);
                float* dst = (which == 0) ? &g_q[h][0][0]
                           : (which == 1) ? &g_k[h][0][0] : &g_v[h][0][0];
                const float s = (which == 0) ? 0.125f : 1.0f;
                *(float2*)&dst[(size_t)row * HD + cc] =
                    make_float2(acc[mi][nj][0] * s, acc[mi][nj][1] * s);
                *(float2*)&dst[(size_t)(row + 8) * HD + cc] =
                    make_float2(acc[mi][nj][2] * s, acc[mi][nj][3] * s);
            } else {
                *(float2*)&C[(size_t)row * N + n] =
                    make_float2(acc[mi][nj][0], acc[mi][nj][1]);
                *(float2*)&C[(size_t)(row + 8) * N + n] =
                    make_float2(acc[mi][nj][2], acc[mi][nj][3]);
            }
        }
}

// ---------------- flash attention (fp32, unchanged) ------------------------
#define FLASH_SMEM_FLOATS (64*64 + 64*65 + 64*64 + 192)
#define FLASH_SMEM_BYTES  (FLASH_SMEM_FLOATS * 4)

__global__ __launch_bounds__(256)
void flash_kernel()
{
    extern __shared__ float sm[];
    float* Qs  = sm;
    float* KP  = Qs + 64 * 64;
    float* Vs  = KP + 64 * 65;
    float* m_s = Vs + 64 * 64;
    float* l_s = m_s + 64;
    float* sc_s = l_s + 64;

    const int h  = blockIdx.y;
    const int qb = blockIdx.x;
    const int tid = threadIdx.x;
    const int ty = tid >> 4, tx = tid & 15;

    const float* Qg = &g_q[h][qb * 64][0];
    #pragma unroll
    for (int it = 0; it < 16; it++) {
        int idx = it * 256 + tid;
        Qs[idx] = Qg[idx];
    }
    if (tid < 64) { m_s[tid] = -1e30f; l_s[tid] = 0.f; }
    float acc[4][4] = {};
    __syncthreads();

    for (int kb = 0; kb < SEQ_T / 64; kb++) {
        const float* Kg = &g_k[h][kb * 64][0];
        const float* Vg = &g_v[h][kb * 64][0];
        #pragma unroll
        for (int it = 0; it < 16; it++) {
            int idx = it * 256 + tid;
            int r = idx >> 6, c = idx & 63;
            KP[r * 65 + c] = Kg[idx];
            Vs[idx]        = Vg[idx];
        }
        __syncthreads();

        float s[4][4] = {};
        #pragma unroll 8
        for (int k = 0; k < 64; k++) {
            float rq[4], rk[4];
            #pragma unroll
            for (int i = 0; i < 4; i++) rq[i] = Qs[(4 * ty + i) * 64 + k];
            #pragma unroll
            for (int j = 0; j < 4; j++) rk[j] = KP[(4 * tx + j) * 65 + k];
            #pragma unroll
            for (int i = 0; i < 4; i++)
                #pragma unroll
                for (int j = 0; j < 4; j++)
                    s[i][j] = fmaf(rq[i], rk[j], s[i][j]);
        }
        __syncthreads();

        #pragma unroll
        for (int i = 0; i < 4; i++)
            #pragma unroll
            for (int j = 0; j < 4; j++)
                KP[(4 * ty + i) * 65 + 4 * tx + j] = s[i][j];
        __syncthreads();

        {
            const int row = tid >> 2, seg = tid & 3;
            float* Pr = &KP[row * 65 + seg * 16];
            float mx = -1e30f;
            #pragma unroll
            for (int c = 0; c < 16; c++) mx = fmaxf(mx, Pr[c]);
            mx = fmaxf(mx, __shfl_xor_sync(0xffffffffu, mx, 1));
            mx = fmaxf(mx, __shfl_xor_sync(0xffffffffu, mx, 2));
            const float m_old = m_s[row];
            const float m_new = fmaxf(m_old, mx);
            float sum = 0.f;
            #pragma unroll
            for (int c = 0; c < 16; c++) {
                float p = __expf(Pr[c] - m_new);
                Pr[c] = p;
                sum += p;
            }
            sum += __shfl_xor_sync(0xffffffffu, sum, 1);
            sum += __shfl_xor_sync(0xffffffffu, sum, 2);
            if (seg == 0) {
                const float corr = __expf(m_old - m_new);
                l_s[row]  = l_s[row] * corr + sum;
                m_s[row]  = m_new;
                sc_s[row] = corr;
            }
        }
        __syncthreads();

        float scl[4];
        #pragma unroll
        for (int i = 0; i < 4; i++) scl[i] = sc_s[4 * ty + i];
        #pragma unroll
        for (int i = 0; i < 4; i++)
            #pragma unroll
            for (int j = 0; j < 4; j++)
                acc[i][j] *= scl[i];

        #pragma unroll 8
        for (int n = 0; n < 64; n++) {
            float rp[4], rv[4];
            #pragma unroll
            for (int i = 0; i < 4; i++) rp[i] = KP[(4 * ty + i) * 65 + n];
            #pragma unroll
            for (int j = 0; j < 4; j++) rv[j] = Vs[n * 64 + 4 * tx + j];
            #pragma unroll
            for (int i = 0; i < 4; i++)
                #pragma unroll
                for (int j = 0; j < 4; j++)
                    acc[i][j] = fmaf(rp[i], rv[j], acc[i][j]);
        }
        __syncthreads();
    }

    float inv[4];
    #pragma unroll
    for (int i = 0; i < 4; i++) inv[i] = 1.0f / l_s[4 * ty + i];
    #pragma unroll
    for (int i = 0; i < 4; i++) {
        const int t = qb * 64 + 4 * ty + i;
        float4 o;
        o.x = acc[i][0] * inv[i];
        o.y = acc[i][1] * inv[i];
        o.z = acc[i][2] * inv[i];
        o.w = acc[i][3] * inv[i];
        *(float4*)&g_y[t][h * 64 + 4 * tx] = o;
    }
}

// ---------------- launch ---------------------------------------------------
extern "C" void kernel_launch(void* const* d_in, const int* in_sizes, int n_in,
                              void* d_out, int out_size)
{
    (void)in_sizes; (void)n_in; (void)out_size;
    const float* x     = (const float*)d_in[0];
    const float* Wqkv  = (const float*)d_in[1];
    const float* Wproj = (const float*)d_in[2];
    float* out = (float*)d_out;

    cudaFuncSetAttribute(flash_kernel, cudaFuncAttributeMaxDynamicSharedMemorySize,
                         FLASH_SMEM_BYTES);
    cudaFuncSetAttribute(mma_gemm_kernel<0>, cudaFuncAttributeMaxDynamicSharedMemorySize,
                         GEMM_SMEM);
    cudaFuncSetAttribute(mma_gemm_kernel<1>, cudaFuncAttributeMaxDynamicSharedMemorySize,
                         GEMM_SMEM);

    conv_split_kernel<0><<<SEQ_T * DIM / 4 / 256, 256>>>(x);
    transpose_split_kernel<0><<<dim3(3 * DIM / 32, DIM / 32), dim3(32, 8)>>>(Wqkv);
    transpose_split_kernel<1><<<dim3(DIM / 32, DIM / 32), dim3(32, 8)>>>(Wproj);

    mma_gemm_kernel<0><<<dim3(3 * DIM / 128, SEQ_T / 128), 256, GEMM_SMEM>>>(
        nullptr, 3 * DIM);

    flash_kernel<<<dim3(SEQ_T / 64, NUM_H), 256, FLASH_SMEM_BYTES>>>();

    conv_split_kernel<1><<<SEQ_T * DIM / 4 / 256, 256>>>(nullptr);
    mma_gemm_kernel<1><<<dim3(DIM / 128, SEQ_T / 128), 256, GEMM_SMEM>>>(
        out, DIM);
}

// round 7
// speedup vs baseline: 2.6892x; 2.0151x over previous
#include <cuda_runtime.h>
#include <cuda_bf16.h>
#include <cstdint>

#define NUM_H 16
#define SEQ_T 2048
#define DIM   1024
#define HD    64

// ---------------- scratch (__device__ globals) -----------------------------
__device__ __align__(16) __nv_bfloat16 gA_hi[SEQ_T][DIM];
__device__ __align__(16) __nv_bfloat16 gA_lo[SEQ_T][DIM];
__device__ __align__(16) __nv_bfloat16 gBq_hi[3 * DIM][DIM];   // [N][K]
__device__ __align__(16) __nv_bfloat16 gBq_lo[3 * DIM][DIM];
__device__ __align__(16) __nv_bfloat16 gBp_hi[DIM][DIM];
__device__ __align__(16) __nv_bfloat16 gBp_lo[DIM][DIM];
__device__ __align__(16) __nv_bfloat16 gY_hi[SEQ_T][DIM];
__device__ __align__(16) __nv_bfloat16 gY_lo[SEQ_T][DIM];

// per-head split Q/K/V (Q pre-scaled by 1/8)
__device__ __align__(16) __nv_bfloat16 gQh[NUM_H][SEQ_T][HD];
__device__ __align__(16) __nv_bfloat16 gQl[NUM_H][SEQ_T][HD];
__device__ __align__(16) __nv_bfloat16 gKh[NUM_H][SEQ_T][HD];
__device__ __align__(16) __nv_bfloat16 gKl[NUM_H][SEQ_T][HD];
__device__ __align__(16) __nv_bfloat16 gVh[NUM_H][SEQ_T][HD];
__device__ __align__(16) __nv_bfloat16 gVl[NUM_H][SEQ_T][HD];

// ---------------- PTX helpers ----------------------------------------------
__device__ __forceinline__ uint32_t smem_u32(const void* p) {
    uint32_t a;
    asm("{ .reg .u64 t; cvta.to.shared.u64 t, %1; cvt.u32.u64 %0, t; }" : "=r"(a) : "l"(p));
    return a;
}
#define CP_ASYNC16(dst, src) \
    asm volatile("cp.async.cg.shared.global [%0], [%1], 16;" :: "r"(dst), "l"(src))
#define CP_COMMIT() asm volatile("cp.async.commit_group;" ::: "memory")
#define CP_WAIT(n)  asm volatile("cp.async.wait_group %0;" :: "n"(n) : "memory")

__device__ __forceinline__ void ldsm4(uint32_t* r, uint32_t addr) {
    asm volatile("ldmatrix.sync.aligned.m8n8.x4.shared.b16 {%0,%1,%2,%3}, [%4];"
        : "=r"(r[0]), "=r"(r[1]), "=r"(r[2]), "=r"(r[3]) : "r"(addr));
}
__device__ __forceinline__ void ldsm4t(uint32_t* r, uint32_t addr) {
    asm volatile("ldmatrix.sync.aligned.m8n8.x4.trans.shared.b16 {%0,%1,%2,%3}, [%4];"
        : "=r"(r[0]), "=r"(r[1]), "=r"(r[2]), "=r"(r[3]) : "r"(addr));
}
__device__ __forceinline__ void mma16816(float* d, const uint32_t* a,
                                         uint32_t b0, uint32_t b1) {
    asm volatile("mma.sync.aligned.m16n8k16.row.col.f32.bf16.bf16.f32 "
        "{%0,%1,%2,%3}, {%4,%5,%6,%7}, {%8,%9}, {%0,%1,%2,%3};"
        : "+f"(d[0]), "+f"(d[1]), "+f"(d[2]), "+f"(d[3])
        : "r"(a[0]), "r"(a[1]), "r"(a[2]), "r"(a[3]), "r"(b0), "r"(b1));
}
// split two floats into packed bf16x2 hi and residual lo
__device__ __forceinline__ void split2(float x, float y, uint32_t& hi, uint32_t& lo) {
    __nv_bfloat16 hx = __float2bfloat16(x), hy = __float2bfloat16(y);
    __nv_bfloat16 lx = __float2bfloat16(x - __bfloat162float(hx));
    __nv_bfloat16 ly = __float2bfloat16(y - __bfloat162float(hy));
    __nv_bfloat162 H(hx, hy), L(lx, ly);
    hi = *(uint32_t*)&H;
    lo = *(uint32_t*)&L;
}

// ---------------- convert kernels ------------------------------------------
__global__ void conv_split_kernel(const float* __restrict__ src)
{
    __nv_bfloat16* hi = &gA_hi[0][0];
    __nv_bfloat16* lo = &gA_lo[0][0];
    int i = (blockIdx.x * blockDim.x + threadIdx.x) * 4;
    float4 v = *(const float4*)(src + i);
    uint32_t h01, l01, h23, l23;
    split2(v.x, v.y, h01, l01);
    split2(v.z, v.w, h23, l23);
    *(uint32_t*)(hi + i)     = h01;
    *(uint32_t*)(hi + i + 2) = h23;
    *(uint32_t*)(lo + i)     = l01;
    *(uint32_t*)(lo + i + 2) = l23;
}

template<int MODE>   // W[K][N] -> out[N][K] hi/lo.  0: W_qkv ; 1: W_proj
__global__ void transpose_split_kernel(const float* __restrict__ W)
{
    const int N = (MODE == 0) ? 3 * DIM : DIM;
    __nv_bfloat16* hi = (MODE == 0) ? &gBq_hi[0][0] : &gBp_hi[0][0];
    __nv_bfloat16* lo = (MODE == 0) ? &gBq_lo[0][0] : &gBp_lo[0][0];
    __shared__ float t[32][33];
    const int n0 = blockIdx.x * 32, k0 = blockIdx.y * 32;
    const int tx = threadIdx.x, ty = threadIdx.y;
    #pragma unroll
    for (int i = ty; i < 32; i += 8)
        t[i][tx] = W[(size_t)(k0 + i) * N + n0 + tx];
    __syncthreads();
    #pragma unroll
    for (int i = ty; i < 32; i += 8) {
        float v = t[tx][i];
        __nv_bfloat16 h = __float2bfloat16(v);
        __nv_bfloat16 l = __float2bfloat16(v - __bfloat162float(h));
        hi[(size_t)(n0 + i) * DIM + k0 + tx] = h;
        lo[(size_t)(n0 + i) * DIM + k0 + tx] = l;
    }
}

// ---------------- warp-mma bf16 3-split GEMM -------------------------------
// MODE 0: A=gA,B=gBq -> split bf16 scatter into gQ/gK/gV (q*0.125)
// MODE 1: A=gY,B=gBp -> fp32 C
#define KCHUNK   32
#define RSTRIDE  40
#define TILE_B   (128 * RSTRIDE * 2)
#define STAGE_B  (4 * TILE_B)
#define GEMM_SMEM (2 * STAGE_B)          // 81920 B

template<int MODE>
__global__ __launch_bounds__(256)
void mma_gemm_kernel(float* __restrict__ C, int N)
{
    extern __shared__ char smem[];
    const uint32_t sb = smem_u32(smem);
    const int tid = threadIdx.x;
    const int bm = blockIdx.y, bn = blockIdx.x;
    const int w = tid >> 5, lane = tid & 31;
    const int wm = w >> 1, wn = w & 1;
    const int lrow = lane & 15, lcol8 = (lane >> 4) * 8;
    const int gid = lane >> 2, tig = lane & 3;

    const __nv_bfloat16* Ahi = (MODE == 0) ? &gA_hi[0][0] : &gY_hi[0][0];
    const __nv_bfloat16* Alo = (MODE == 0) ? &gA_lo[0][0] : &gY_lo[0][0];
    const __nv_bfloat16* Bhi = (MODE == 0) ? &gBq_hi[0][0] : &gBp_hi[0][0];
    const __nv_bfloat16* Blo = (MODE == 0) ? &gBq_lo[0][0] : &gBp_lo[0][0];
    const __nv_bfloat16* srcs[4] = { Ahi, Alo, Bhi, Blo };

    int cp_tile[8], cp_row[8], cp_seg[8];
    #pragma unroll
    for (int it = 0; it < 8; ++it) {
        int idx = it * 256 + tid;
        cp_tile[it] = idx >> 9;
        cp_row[it]  = (idx & 511) >> 2;
        cp_seg[it]  = idx & 3;
    }

    auto issue_load = [&](int c) {
        const uint32_t st = sb + (uint32_t)(c & 1) * STAGE_B;
        const int k0 = c * KCHUNK;
        #pragma unroll
        for (int it = 0; it < 8; ++it) {
            const int t = cp_tile[it];
            const int rbase = ((t < 2) ? bm : bn) * 128;
            const __nv_bfloat16* src = srcs[t]
                + (size_t)(rbase + cp_row[it]) * DIM + k0 + cp_seg[it] * 8;
            const uint32_t dst = st + t * TILE_B + cp_row[it] * (RSTRIDE * 2)
                               + cp_seg[it] * 16;
            CP_ASYNC16(dst, src);
        }
        CP_COMMIT();
    };

    float acc[2][8][4] = {};

    issue_load(0);
    const int NCHUNK = DIM / KCHUNK;
    for (int c = 0; c < NCHUNK; ++c) {
        if (c + 1 < NCHUNK) { issue_load(c + 1); CP_WAIT(1); }
        else                { CP_WAIT(0); }
        __syncthreads();

        const uint32_t st = sb + (uint32_t)(c & 1) * STAGE_B;
        const uint32_t aH = st, aL = st + TILE_B, bH = st + 2 * TILE_B, bL = st + 3 * TILE_B;

        #pragma unroll
        for (int kk = 0; kk < 2; ++kk) {
            const uint32_t koff = (kk * 16 + lcol8) * 2;
            uint32_t ah[2][4], al[2][4], bh[4][4], bl[4][4];
            #pragma unroll
            for (int mi = 0; mi < 2; ++mi) {
                const uint32_t ro = (wm * 32 + mi * 16 + lrow) * (RSTRIDE * 2) + koff;
                ldsm4(ah[mi], aH + ro);
                ldsm4(al[mi], aL + ro);
            }
            #pragma unroll
            for (int nq = 0; nq < 4; ++nq) {
                const uint32_t ro = (wn * 64 + nq * 16 + lrow) * (RSTRIDE * 2) + koff;
                ldsm4(bh[nq], bH + ro);
                ldsm4(bl[nq], bL + ro);
            }
            #pragma unroll
            for (int mi = 0; mi < 2; ++mi)
                #pragma unroll
                for (int nq = 0; nq < 4; ++nq) {
                    mma16816(acc[mi][nq * 2 + 0], ah[mi], bh[nq][0], bh[nq][2]);
                    mma16816(acc[mi][nq * 2 + 1], ah[mi], bh[nq][1], bh[nq][3]);
                    mma16816(acc[mi][nq * 2 + 0], ah[mi], bl[nq][0], bl[nq][2]);
                    mma16816(acc[mi][nq * 2 + 1], ah[mi], bl[nq][1], bl[nq][3]);
                    mma16816(acc[mi][nq * 2 + 0], al[mi], bh[nq][0], bh[nq][2]);
                    mma16816(acc[mi][nq * 2 + 1], al[mi], bh[nq][1], bh[nq][3]);
                }
        }
        __syncthreads();
    }

    #pragma unroll
    for (int mi = 0; mi < 2; ++mi)
        #pragma unroll
        for (int nj = 0; nj < 8; ++nj) {
            const int row = bm * 128 + wm * 32 + mi * 16 + gid;
            const int n = bn * 128 + wn * 64 + nj * 8 + tig * 2;
            if (MODE == 0) {
                const int which = n >> 10;
                const int h = (n >> 6) & (NUM_H - 1);
                const int cc = n & (HD - 1);
                __nv_bfloat16* dh = (which == 0) ? &gQh[h][0][0]
                                  : (which == 1) ? &gKh[h][0][0] : &gVh[h][0][0];
                __nv_bfloat16* dl = (which == 0) ? &gQl[h][0][0]
                                  : (which == 1) ? &gKl[h][0][0] : &gVl[h][0][0];
                const float s = (which == 0) ? 0.125f : 1.0f;
                uint32_t hi, lo;
                split2(acc[mi][nj][0] * s, acc[mi][nj][1] * s, hi, lo);
                *(uint32_t*)&dh[(size_t)row * HD + cc] = hi;
                *(uint32_t*)&dl[(size_t)row * HD + cc] = lo;
                split2(acc[mi][nj][2] * s, acc[mi][nj][3] * s, hi, lo);
                *(uint32_t*)&dh[(size_t)(row + 8) * HD + cc] = hi;
                *(uint32_t*)&dl[(size_t)(row + 8) * HD + cc] = lo;
            } else {
                *(float2*)&C[(size_t)row * N + n] =
                    make_float2(acc[mi][nj][0], acc[mi][nj][1]);
                *(float2*)&C[(size_t)(row + 8) * N + n] =
                    make_float2(acc[mi][nj][2], acc[mi][nj][3]);
            }
        }
}

// ---------------- flash attention, bf16 mma 3-split ------------------------
// CTA: 128 queries x 1 head. 8 warps, warp w owns rows 16w..16w+15.
// Bc=64 keys per iteration, double-buffered Kh/Kl/Vh/Vl via cp.async.
#define BR 128
#define BC 64
#define FSTR 72                                // smem row stride in halves
#define Q_TILE_H  (BR * FSTR)                  // 9216 halves
#define KV_TILE_H (BC * FSTR)                  // 4608 halves
#define STAGE_H   (4 * KV_TILE_H)              // 18432 halves
#define FLASH_SMEM_B ((2 * Q_TILE_H + 2 * STAGE_H) * 2)   // 110592 B

__global__ __launch_bounds__(256)
void flash_mma_kernel()
{
    extern __shared__ char fsm[];
    const uint32_t sb = smem_u32(fsm);
    const int tid = threadIdx.x;
    const int qb = blockIdx.x, h = blockIdx.y;
    const int w = tid >> 5, lane = tid & 31;
    const int gid = lane >> 2, tig = lane & 3;
    const int l15 = lane & 15, l16 = lane >> 4;

    // one-time Q load (Qh | Ql), own commit group
    #pragma unroll
    for (int it = 0; it < 8; ++it) {
        int idx = it * 256 + tid;
        int tile = idx >> 10, r = (idx >> 3) & 127, ch = idx & 7;
        const __nv_bfloat16* src = tile == 0 ? &gQh[h][qb * BR + r][ch * 8]
                                             : &gQl[h][qb * BR + r][ch * 8];
        CP_ASYNC16(sb + (tile * Q_TILE_H + r * FSTR + ch * 8) * 2, src);
    }
    CP_COMMIT();

    auto load_kv = [&](int kb) {
        const uint32_t st = sb + (2 * Q_TILE_H + (uint32_t)(kb & 1) * STAGE_H) * 2;
        #pragma unroll
        for (int it = 0; it < 8; ++it) {
            int idx = it * 256 + tid;
            int tile = idx >> 9, r = (idx >> 3) & 63, ch = idx & 7;
            const int tg = kb * BC + r;
            const __nv_bfloat16* src =
                (tile == 0) ? &gKh[h][tg][ch * 8] :
                (tile == 1) ? &gKl[h][tg][ch * 8] :
                (tile == 2) ? &gVh[h][tg][ch * 8] : &gVl[h][tg][ch * 8];
            CP_ASYNC16(st + (tile * KV_TILE_H + r * FSTR + ch * 8) * 2, src);
        }
        CP_COMMIT();
    };

    float o[8][4] = {};
    float m0 = -1e30f, m1 = -1e30f, l0 = 0.f, l1 = 0.f;

    load_kv(0);
    const int NKB = SEQ_T / BC;                 // 32
    for (int kb = 0; kb < NKB; ++kb) {
        if (kb + 1 < NKB) { load_kv(kb + 1); CP_WAIT(1); }
        else              { CP_WAIT(0); }
        __syncthreads();

        const uint32_t qh_b = sb, ql_b = sb + Q_TILE_H * 2;
        const uint32_t st = sb + (2 * Q_TILE_H + (uint32_t)(kb & 1) * STAGE_H) * 2;
        const uint32_t kh_b = st;
        const uint32_t kl_b = st + KV_TILE_H * 2;
        const uint32_t vh_b = st + 2 * KV_TILE_H * 2;
        const uint32_t vl_b = st + 3 * KV_TILE_H * 2;

        // ---- S = Q K^T (3-split) ----
        float s[8][4] = {};
        #pragma unroll
        for (int ks = 0; ks < 4; ++ks) {
            const uint32_t qoff = ((w * 16 + l15) * FSTR + ks * 16 + l16 * 8) * 2;
            uint32_t qh[4], ql[4];
            ldsm4(qh, qh_b + qoff);
            ldsm4(ql, ql_b + qoff);
            #pragma unroll
            for (int kg = 0; kg < 4; ++kg) {
                const uint32_t koff = ((kg * 16 + l15) * FSTR + ks * 16 + l16 * 8) * 2;
                uint32_t kh[4], kl[4];
                ldsm4(kh, kh_b + koff);
                ldsm4(kl, kl_b + koff);
                mma16816(s[2 * kg],     qh, kh[0], kh[2]);
                mma16816(s[2 * kg + 1], qh, kh[1], kh[3]);
                mma16816(s[2 * kg],     qh, kl[0], kl[2]);
                mma16816(s[2 * kg + 1], qh, kl[1], kl[3]);
                mma16816(s[2 * kg],     ql, kh[0], kh[2]);
                mma16816(s[2 * kg + 1], ql, kh[1], kh[3]);
            }
        }

        // ---- online softmax (rows gid and gid+8 of this warp) ----
        float mx0 = -1e30f, mx1 = -1e30f;
        #pragma unroll
        for (int nf = 0; nf < 8; ++nf) {
            mx0 = fmaxf(mx0, fmaxf(s[nf][0], s[nf][1]));
            mx1 = fmaxf(mx1, fmaxf(s[nf][2], s[nf][3]));
        }
        mx0 = fmaxf(mx0, __shfl_xor_sync(0xffffffffu, mx0, 1));
        mx0 = fmaxf(mx0, __shfl_xor_sync(0xffffffffu, mx0, 2));
        mx1 = fmaxf(mx1, __shfl_xor_sync(0xffffffffu, mx1, 1));
        mx1 = fmaxf(mx1, __shfl_xor_sync(0xffffffffu, mx1, 2));
        const float mn0 = fmaxf(m0, mx0), mn1 = fmaxf(m1, mx1);
        const float c0 = __expf(m0 - mn0), c1 = __expf(m1 - mn1);
        m0 = mn0; m1 = mn1;
        float sum0 = 0.f, sum1 = 0.f;
        #pragma unroll
        for (int nf = 0; nf < 8; ++nf) {
            s[nf][0] = __expf(s[nf][0] - mn0);
            s[nf][1] = __expf(s[nf][1] - mn0);
            s[nf][2] = __expf(s[nf][2] - mn1);
            s[nf][3] = __expf(s[nf][3] - mn1);
            sum0 += s[nf][0] + s[nf][1];
            sum1 += s[nf][2] + s[nf][3];
        }
        sum0 += __shfl_xor_sync(0xffffffffu, sum0, 1);
        sum0 += __shfl_xor_sync(0xffffffffu, sum0, 2);
        sum1 += __shfl_xor_sync(0xffffffffu, sum1, 1);
        sum1 += __shfl_xor_sync(0xffffffffu, sum1, 2);
        l0 = l0 * c0 + sum0;
        l1 = l1 * c1 + sum1;
        #pragma unroll
        for (int nf = 0; nf < 8; ++nf) {
            o[nf][0] *= c0; o[nf][1] *= c0;
            o[nf][2] *= c1; o[nf][3] *= c1;
        }

        // ---- O += P V (3-split; P from S accumulator, V via ldmatrix.trans)
        #pragma unroll
        for (int ks = 0; ks < 4; ++ks) {
            uint32_t ph[4], pl[4];
            split2(s[2 * ks][0],     s[2 * ks][1],     ph[0], pl[0]);
            split2(s[2 * ks][2],     s[2 * ks][3],     ph[1], pl[1]);
            split2(s[2 * ks + 1][0], s[2 * ks + 1][1], ph[2], pl[2]);
            split2(s[2 * ks + 1][2], s[2 * ks + 1][3], ph[3], pl[3]);
            #pragma unroll
            for (int hg = 0; hg < 4; ++hg) {
                const uint32_t voff = ((ks * 16 + l15) * FSTR + hg * 16 + l16 * 8) * 2;
                uint32_t vh[4], vl[4];
                ldsm4t(vh, vh_b + voff);
                ldsm4t(vl, vl_b + voff);
                mma16816(o[2 * hg],     ph, vh[0], vh[1]);
                mma16816(o[2 * hg + 1], ph, vh[2], vh[3]);
                mma16816(o[2 * hg],     ph, vl[0], vl[1]);
                mma16816(o[2 * hg + 1], ph, vl[2], vl[3]);
                mma16816(o[2 * hg],     pl, vh[0], vh[1]);
                mma16816(o[2 * hg + 1], pl, vh[2], vh[3]);
            }
        }
        __syncthreads();
    }

    // ---- epilogue: y = O / l, split to gY hi/lo ----
    const float i0 = 1.0f / l0, i1 = 1.0f / l1;
    const int t0 = qb * BR + w * 16 + gid;
    #pragma unroll
    for (int nf = 0; nf < 8; ++nf) {
        const int col = h * 64 + nf * 8 + 2 * tig;
        uint32_t hi, lo;
        split2(o[nf][0] * i0, o[nf][1] * i0, hi, lo);
        *(uint32_t*)&gY_hi[t0][col] = hi;
        *(uint32_t*)&gY_lo[t0][col] = lo;
        split2(o[nf][2] * i1, o[nf][3] * i1, hi, lo);
        *(uint32_t*)&gY_hi[t0 + 8][col] = hi;
        *(uint32_t*)&gY_lo[t0 + 8][col] = lo;
    }
}

// ---------------- launch ---------------------------------------------------
extern "C" void kernel_launch(void* const* d_in, const int* in_sizes, int n_in,
                              void* d_out, int out_size)
{
    (void)in_sizes; (void)n_in; (void)out_size;
    const float* x     = (const float*)d_in[0];
    const float* Wqkv  = (const float*)d_in[1];
    const float* Wproj = (const float*)d_in[2];
    float* out = (float*)d_out;

    cudaFuncSetAttribute(mma_gemm_kernel<0>, cudaFuncAttributeMaxDynamicSharedMemorySize,
                         GEMM_SMEM);
    cudaFuncSetAttribute(mma_gemm_kernel<1>, cudaFuncAttributeMaxDynamicSharedMemorySize,
                         GEMM_SMEM);
    cudaFuncSetAttribute(flash_mma_kernel, cudaFuncAttributeMaxDynamicSharedMemorySize,
                         FLASH_SMEM_B);

    conv_split_kernel<<<SEQ_T * DIM / 4 / 256, 256>>>(x);
    transpose_split_kernel<0><<<dim3(3 * DIM / 32, DIM / 32), dim3(32, 8)>>>(Wqkv);
    transpose_split_kernel<1><<<dim3(DIM / 32, DIM / 32), dim3(32, 8)>>>(Wproj);

    // QKV = x @ W_qkv, split-scattered into gQ/gK/gV
    mma_gemm_kernel<0><<<dim3(3 * DIM / 128, SEQ_T / 128), 256, GEMM_SMEM>>>(
        nullptr, 3 * DIM);

    // fused attention -> gY hi/lo
    flash_mma_kernel<<<dim3(SEQ_T / BR, NUM_H), 256, FLASH_SMEM_B>>>();

    // out = y @ W_proj
    mma_gemm_kernel<1><<<dim3(DIM / 128, SEQ_T / 128), 256, GEMM_SMEM>>>(
        out, DIM);
}

// round 8
// speedup vs baseline: 2.7030x; 1.0051x over previous
#include <cuda_runtime.h>
#include <cuda_bf16.h>
#include <cstdint>

#define NUM_H 16
#define SEQ_T 2048
#define DIM   1024
#define HD    64

// ---------------- scratch (__device__ globals) -----------------------------
__device__ __align__(16) __nv_bfloat16 gA_hi[SEQ_T][DIM];
__device__ __align__(16) __nv_bfloat16 gA_lo[SEQ_T][DIM];
__device__ __align__(16) __nv_bfloat16 gBq_hi[3 * DIM][DIM];   // [N][K]
__device__ __align__(16) __nv_bfloat16 gBq_lo[3 * DIM][DIM];
__device__ __align__(16) __nv_bfloat16 gBp_hi[DIM][DIM];
__device__ __align__(16) __nv_bfloat16 gBp_lo[DIM][DIM];
__device__ __align__(16) __nv_bfloat16 gY_hi[SEQ_T][DIM];
__device__ __align__(16) __nv_bfloat16 gY_lo[SEQ_T][DIM];

// per-head split Q/K/V (Q pre-scaled by 1/8)
__device__ __align__(16) __nv_bfloat16 gQh[NUM_H][SEQ_T][HD];
__device__ __align__(16) __nv_bfloat16 gQl[NUM_H][SEQ_T][HD];
__device__ __align__(16) __nv_bfloat16 gKh[NUM_H][SEQ_T][HD];
__device__ __align__(16) __nv_bfloat16 gKl[NUM_H][SEQ_T][HD];
__device__ __align__(16) __nv_bfloat16 gVh[NUM_H][SEQ_T][HD];
__device__ __align__(16) __nv_bfloat16 gVl[NUM_H][SEQ_T][HD];

// ---------------- PTX helpers ----------------------------------------------
__device__ __forceinline__ uint32_t smem_u32(const void* p) {
    uint32_t a;
    asm("{ .reg .u64 t; cvta.to.shared.u64 t, %1; cvt.u32.u64 %0, t; }" : "=r"(a) : "l"(p));
    return a;
}
#define CP_ASYNC16(dst, src) \
    asm volatile("cp.async.cg.shared.global [%0], [%1], 16;" :: "r"(dst), "l"(src))
#define CP_COMMIT() asm volatile("cp.async.commit_group;" ::: "memory")
#define CP_WAIT(n)  asm volatile("cp.async.wait_group %0;" :: "n"(n) : "memory")

__device__ __forceinline__ void ldsm4(uint32_t* r, uint32_t addr) {
    asm volatile("ldmatrix.sync.aligned.m8n8.x4.shared.b16 {%0,%1,%2,%3}, [%4];"
        : "=r"(r[0]), "=r"(r[1]), "=r"(r[2]), "=r"(r[3]) : "r"(addr));
}
__device__ __forceinline__ void ldsm4t(uint32_t* r, uint32_t addr) {
    asm volatile("ldmatrix.sync.aligned.m8n8.x4.trans.shared.b16 {%0,%1,%2,%3}, [%4];"
        : "=r"(r[0]), "=r"(r[1]), "=r"(r[2]), "=r"(r[3]) : "r"(addr));
}
__device__ __forceinline__ void mma16816(float* d, const uint32_t* a,
                                         uint32_t b0, uint32_t b1) {
    asm volatile("mma.sync.aligned.m16n8k16.row.col.f32.bf16.bf16.f32 "
        "{%0,%1,%2,%3}, {%4,%5,%6,%7}, {%8,%9}, {%0,%1,%2,%3};"
        : "+f"(d[0]), "+f"(d[1]), "+f"(d[2]), "+f"(d[3])
        : "r"(a[0]), "r"(a[1]), "r"(a[2]), "r"(a[3]), "r"(b0), "r"(b1));
}
// split two floats into packed bf16x2 hi and residual lo
__device__ __forceinline__ void split2(float x, float y, uint32_t& hi, uint32_t& lo) {
    __nv_bfloat16 hx = __float2bfloat16(x), hy = __float2bfloat16(y);
    __nv_bfloat16 lx = __float2bfloat16(x - __bfloat162float(hx));
    __nv_bfloat16 ly = __float2bfloat16(y - __bfloat162float(hy));
    __nv_bfloat162 H(hx, hy), L(lx, ly);
    hi = *(uint32_t*)&H;
    lo = *(uint32_t*)&L;
}

// ---------------- convert kernels ------------------------------------------
__global__ void conv_split_kernel(const float* __restrict__ src)
{
    __nv_bfloat16* hi = &gA_hi[0][0];
    __nv_bfloat16* lo = &gA_lo[0][0];
    int i = (blockIdx.x * blockDim.x + threadIdx.x) * 4;
    float4 v = *(const float4*)(src + i);
    uint32_t h01, l01, h23, l23;
    split2(v.x, v.y, h01, l01);
    split2(v.z, v.w, h23, l23);
    *(uint32_t*)(hi + i)     = h01;
    *(uint32_t*)(hi + i + 2) = h23;
    *(uint32_t*)(lo + i)     = l01;
    *(uint32_t*)(lo + i + 2) = l23;
}

template<int MODE>   // W[K][N] -> out[N][K] hi/lo.  0: W_qkv ; 1: W_proj
__global__ void transpose_split_kernel(const float* __restrict__ W)
{
    const int N = (MODE == 0) ? 3 * DIM : DIM;
    __nv_bfloat16* hi = (MODE == 0) ? &gBq_hi[0][0] : &gBp_hi[0][0];
    __nv_bfloat16* lo = (MODE == 0) ? &gBq_lo[0][0] : &gBp_lo[0][0];
    __shared__ float t[32][33];
    const int n0 = blockIdx.x * 32, k0 = blockIdx.y * 32;
    const int tx = threadIdx.x, ty = threadIdx.y;
    #pragma unroll
    for (int i = ty; i < 32; i += 8)
        t[i][tx] = W[(size_t)(k0 + i) * N + n0 + tx];
    __syncthreads();
    #pragma unroll
    for (int i = ty; i < 32; i += 8) {
        float v = t[tx][i];
        __nv_bfloat16 h = __float2bfloat16(v);
        __nv_bfloat16 l = __float2bfloat16(v - __bfloat162float(h));
        hi[(size_t)(n0 + i) * DIM + k0 + tx] = h;
        lo[(size_t)(n0 + i) * DIM + k0 + tx] = l;
    }
}

// ---------------- warp-mma bf16 3-split GEMM -------------------------------
// MODE 0: A=gA,B=gBq -> split bf16 scatter into gQ/gK/gV (q*0.125)
// MODE 1: A=gY,B=gBp -> fp32 C
#define KCHUNK   32
#define RSTRIDE  40
#define TILE_B   (128 * RSTRIDE * 2)
#define STAGE_B  (4 * TILE_B)
#define GEMM_SMEM (2 * STAGE_B)          // 81920 B

template<int MODE>
__global__ __launch_bounds__(256)
void mma_gemm_kernel(float* __restrict__ C, int N)
{
    extern __shared__ char smem[];
    const uint32_t sb = smem_u32(smem);
    const int tid = threadIdx.x;
    const int bm = blockIdx.y, bn = blockIdx.x;
    const int w = tid >> 5, lane = tid & 31;
    const int wm = w >> 1, wn = w & 1;
    const int lrow = lane & 15, lcol8 = (lane >> 4) * 8;
    const int gid = lane >> 2, tig = lane & 3;

    const __nv_bfloat16* Ahi = (MODE == 0) ? &gA_hi[0][0] : &gY_hi[0][0];
    const __nv_bfloat16* Alo = (MODE == 0) ? &gA_lo[0][0] : &gY_lo[0][0];
    const __nv_bfloat16* Bhi = (MODE == 0) ? &gBq_hi[0][0] : &gBp_hi[0][0];
    const __nv_bfloat16* Blo = (MODE == 0) ? &gBq_lo[0][0] : &gBp_lo[0][0];
    const __nv_bfloat16* srcs[4] = { Ahi, Alo, Bhi, Blo };

    int cp_tile[8], cp_row[8], cp_seg[8];
    #pragma unroll
    for (int it = 0; it < 8; ++it) {
        int idx = it * 256 + tid;
        cp_tile[it] = idx >> 9;
        cp_row[it]  = (idx & 511) >> 2;
        cp_seg[it]  = idx & 3;
    }

    auto issue_load = [&](int c) {
        const uint32_t st = sb + (uint32_t)(c & 1) * STAGE_B;
        const int k0 = c * KCHUNK;
        #pragma unroll
        for (int it = 0; it < 8; ++it) {
            const int t = cp_tile[it];
            const int rbase = ((t < 2) ? bm : bn) * 128;
            const __nv_bfloat16* src = srcs[t]
                + (size_t)(rbase + cp_row[it]) * DIM + k0 + cp_seg[it] * 8;
            const uint32_t dst = st + t * TILE_B + cp_row[it] * (RSTRIDE * 2)
                               + cp_seg[it] * 16;
            CP_ASYNC16(dst, src);
        }
        CP_COMMIT();
    };

    float acc[2][8][4] = {};

    issue_load(0);
    const int NCHUNK = DIM / KCHUNK;
    for (int c = 0; c < NCHUNK; ++c) {
        if (c + 1 < NCHUNK) { issue_load(c + 1); CP_WAIT(1); }
        else                { CP_WAIT(0); }
        __syncthreads();

        const uint32_t st = sb + (uint32_t)(c & 1) * STAGE_B;
        const uint32_t aH = st, aL = st + TILE_B, bH = st + 2 * TILE_B, bL = st + 3 * TILE_B;

        #pragma unroll
        for (int kk = 0; kk < 2; ++kk) {
            const uint32_t koff = (kk * 16 + lcol8) * 2;
            uint32_t ah[2][4], al[2][4], bh[4][4], bl[4][4];
            #pragma unroll
            for (int mi = 0; mi < 2; ++mi) {
                const uint32_t ro = (wm * 32 + mi * 16 + lrow) * (RSTRIDE * 2) + koff;
                ldsm4(ah[mi], aH + ro);
                ldsm4(al[mi], aL + ro);
            }
            #pragma unroll
            for (int nq = 0; nq < 4; ++nq) {
                const uint32_t ro = (wn * 64 + nq * 16 + lrow) * (RSTRIDE * 2) + koff;
                ldsm4(bh[nq], bH + ro);
                ldsm4(bl[nq], bL + ro);
            }
            // pass 1: Ah x Bh  (each acc touched once per pass -> reuse dist 16)
            #pragma unroll
            for (int mi = 0; mi < 2; ++mi)
                #pragma unroll
                for (int nq = 0; nq < 4; ++nq) {
                    mma16816(acc[mi][nq * 2 + 0], ah[mi], bh[nq][0], bh[nq][2]);
                    mma16816(acc[mi][nq * 2 + 1], ah[mi], bh[nq][1], bh[nq][3]);
                }
            // pass 2: Ah x Bl
            #pragma unroll
            for (int mi = 0; mi < 2; ++mi)
                #pragma unroll
                for (int nq = 0; nq < 4; ++nq) {
                    mma16816(acc[mi][nq * 2 + 0], ah[mi], bl[nq][0], bl[nq][2]);
                    mma16816(acc[mi][nq * 2 + 1], ah[mi], bl[nq][1], bl[nq][3]);
                }
            // pass 3: Al x Bh
            #pragma unroll
            for (int mi = 0; mi < 2; ++mi)
                #pragma unroll
                for (int nq = 0; nq < 4; ++nq) {
                    mma16816(acc[mi][nq * 2 + 0], al[mi], bh[nq][0], bh[nq][2]);
                    mma16816(acc[mi][nq * 2 + 1], al[mi], bh[nq][1], bh[nq][3]);
                }
        }
        __syncthreads();
    }

    #pragma unroll
    for (int mi = 0; mi < 2; ++mi)
        #pragma unroll
        for (int nj = 0; nj < 8; ++nj) {
            const int row = bm * 128 + wm * 32 + mi * 16 + gid;
            const int n = bn * 128 + wn * 64 + nj * 8 + tig * 2;
            if (MODE == 0) {
                const int which = n >> 10;
                const int h = (n >> 6) & (NUM_H - 1);
                const int cc = n & (HD - 1);
                __nv_bfloat16* dh = (which == 0) ? &gQh[h][0][0]
                                  : (which == 1) ? &gKh[h][0][0] : &gVh[h][0][0];
                __nv_bfloat16* dl = (which == 0) ? &gQl[h][0][0]
                                  : (which == 1) ? &gKl[h][0][0] : &gVl[h][0][0];
                const float s = (which == 0) ? 0.125f : 1.0f;
                uint32_t hi, lo;
                split2(acc[mi][nj][0] * s, acc[mi][nj][1] * s, hi, lo);
                *(uint32_t*)&dh[(size_t)row * HD + cc] = hi;
                *(uint32_t*)&dl[(size_t)row * HD + cc] = lo;
                split2(acc[mi][nj][2] * s, acc[mi][nj][3] * s, hi, lo);
                *(uint32_t*)&dh[(size_t)(row + 8) * HD + cc] = hi;
                *(uint32_t*)&dl[(size_t)(row + 8) * HD + cc] = lo;
            } else {
                *(float2*)&C[(size_t)row * N + n] =
                    make_float2(acc[mi][nj][0], acc[mi][nj][1]);
                *(float2*)&C[(size_t)(row + 8) * N + n] =
                    make_float2(acc[mi][nj][2], acc[mi][nj][3]);
            }
        }
}

// ---------------- flash attention, bf16 mma 3-split ------------------------
// CTA: 128 queries x 1 head. 8 warps, warp w owns rows 16w..16w+15.
// Bc=64 keys per iteration, double-buffered Kh/Kl/Vh/Vl via cp.async.
#define BR 128
#define BC 64
#define FSTR 72                                // smem row stride in halves
#define Q_TILE_H  (BR * FSTR)                  // 9216 halves
#define KV_TILE_H (BC * FSTR)                  // 4608 halves
#define STAGE_H   (4 * KV_TILE_H)              // 18432 halves
#define FLASH_SMEM_B ((2 * Q_TILE_H + 2 * STAGE_H) * 2)   // 110592 B

__global__ __launch_bounds__(256)
void flash_mma_kernel()
{
    extern __shared__ char fsm[];
    const uint32_t sb = smem_u32(fsm);
    const int tid = threadIdx.x;
    const int qb = blockIdx.x, h = blockIdx.y;
    const int w = tid >> 5, lane = tid & 31;
    const int gid = lane >> 2, tig = lane & 3;
    const int l15 = lane & 15, l16 = lane >> 4;

    // one-time Q load (Qh | Ql), own commit group
    #pragma unroll
    for (int it = 0; it < 8; ++it) {
        int idx = it * 256 + tid;
        int tile = idx >> 10, r = (idx >> 3) & 127, ch = idx & 7;
        const __nv_bfloat16* src = tile == 0 ? &gQh[h][qb * BR + r][ch * 8]
                                             : &gQl[h][qb * BR + r][ch * 8];
        CP_ASYNC16(sb + (tile * Q_TILE_H + r * FSTR + ch * 8) * 2, src);
    }
    CP_COMMIT();

    auto load_kv = [&](int kb) {
        const uint32_t st = sb + (2 * Q_TILE_H + (uint32_t)(kb & 1) * STAGE_H) * 2;
        #pragma unroll
        for (int it = 0; it < 8; ++it) {
            int idx = it * 256 + tid;
            int tile = idx >> 9, r = (idx >> 3) & 63, ch = idx & 7;
            const int tg = kb * BC + r;
            const __nv_bfloat16* src =
                (tile == 0) ? &gKh[h][tg][ch * 8] :
                (tile == 1) ? &gKl[h][tg][ch * 8] :
                (tile == 2) ? &gVh[h][tg][ch * 8] : &gVl[h][tg][ch * 8];
            CP_ASYNC16(st + (tile * KV_TILE_H + r * FSTR + ch * 8) * 2, src);
        }
        CP_COMMIT();
    };

    float o[8][4] = {};
    float m0 = -1e30f, m1 = -1e30f, l0 = 0.f, l1 = 0.f;

    load_kv(0);
    const int NKB = SEQ_T / BC;                 // 32
    for (int kb = 0; kb < NKB; ++kb) {
        if (kb + 1 < NKB) { load_kv(kb + 1); CP_WAIT(1); }
        else              { CP_WAIT(0); }
        __syncthreads();

        const uint32_t qh_b = sb, ql_b = sb + Q_TILE_H * 2;
        const uint32_t st = sb + (2 * Q_TILE_H + (uint32_t)(kb & 1) * STAGE_H) * 2;
        const uint32_t kh_b = st;
        const uint32_t kl_b = st + KV_TILE_H * 2;
        const uint32_t vh_b = st + 2 * KV_TILE_H * 2;
        const uint32_t vl_b = st + 3 * KV_TILE_H * 2;

        // ---- S = Q K^T (3-split, pass-reordered) ----
        float s[8][4] = {};
        #pragma unroll
        for (int ks = 0; ks < 4; ++ks) {
            const uint32_t qoff = ((w * 16 + l15) * FSTR + ks * 16 + l16 * 8) * 2;
            uint32_t qh[4], ql[4];
            ldsm4(qh, qh_b + qoff);
            ldsm4(ql, ql_b + qoff);
            uint32_t kh[4][4], kl[4][4];
            #pragma unroll
            for (int kg = 0; kg < 4; ++kg) {
                const uint32_t koff = ((kg * 16 + l15) * FSTR + ks * 16 + l16 * 8) * 2;
                ldsm4(kh[kg], kh_b + koff);
                ldsm4(kl[kg], kl_b + koff);
            }
            // pass 1: Qh x Kh
            #pragma unroll
            for (int kg = 0; kg < 4; ++kg) {
                mma16816(s[2 * kg],     qh, kh[kg][0], kh[kg][2]);
                mma16816(s[2 * kg + 1], qh, kh[kg][1], kh[kg][3]);
            }
            // pass 2: Qh x Kl
            #pragma unroll
            for (int kg = 0; kg < 4; ++kg) {
                mma16816(s[2 * kg],     qh, kl[kg][0], kl[kg][2]);
                mma16816(s[2 * kg + 1], qh, kl[kg][1], kl[kg][3]);
            }
            // pass 3: Ql x Kh
            #pragma unroll
            for (int kg = 0; kg < 4; ++kg) {
                mma16816(s[2 * kg],     ql, kh[kg][0], kh[kg][2]);
                mma16816(s[2 * kg + 1], ql, kh[kg][1], kh[kg][3]);
            }
        }

        // ---- online softmax (rows gid and gid+8 of this warp) ----
        float mx0 = -1e30f, mx1 = -1e30f;
        #pragma unroll
        for (int nf = 0; nf < 8; ++nf) {
            mx0 = fmaxf(mx0, fmaxf(s[nf][0], s[nf][1]));
            mx1 = fmaxf(mx1, fmaxf(s[nf][2], s[nf][3]));
        }
        mx0 = fmaxf(mx0, __shfl_xor_sync(0xffffffffu, mx0, 1));
        mx0 = fmaxf(mx0, __shfl_xor_sync(0xffffffffu, mx0, 2));
        mx1 = fmaxf(mx1, __shfl_xor_sync(0xffffffffu, mx1, 1));
        mx1 = fmaxf(mx1, __shfl_xor_sync(0xffffffffu, mx1, 2));
        const float mn0 = fmaxf(m0, mx0), mn1 = fmaxf(m1, mx1);
        const float c0 = __expf(m0 - mn0), c1 = __expf(m1 - mn1);
        m0 = mn0; m1 = mn1;
        float sum0 = 0.f, sum1 = 0.f;
        #pragma unroll
        for (int nf = 0; nf < 8; ++nf) {
            s[nf][0] = __expf(s[nf][0] - mn0);
            s[nf][1] = __expf(s[nf][1] - mn0);
            s[nf][2] = __expf(s[nf][2] - mn1);
            s[nf][3] = __expf(s[nf][3] - mn1);
            sum0 += s[nf][0] + s[nf][1];
            sum1 += s[nf][2] + s[nf][3];
        }
        sum0 += __shfl_xor_sync(0xffffffffu, sum0, 1);
        sum0 += __shfl_xor_sync(0xffffffffu, sum0, 2);
        sum1 += __shfl_xor_sync(0xffffffffu, sum1, 1);
        sum1 += __shfl_xor_sync(0xffffffffu, sum1, 2);
        l0 = l0 * c0 + sum0;
        l1 = l1 * c1 + sum1;
        #pragma unroll
        for (int nf = 0; nf < 8; ++nf) {
            o[nf][0] *= c0; o[nf][1] *= c0;
            o[nf][2] *= c1; o[nf][3] *= c1;
        }

        // ---- O += P V (3-split, pass-reordered; V via ldmatrix.trans) ----
        #pragma unroll
        for (int ks = 0; ks < 4; ++ks) {
            uint32_t ph[4], pl[4];
            split2(s[2 * ks][0],     s[2 * ks][1],     ph[0], pl[0]);
            split2(s[2 * ks][2],     s[2 * ks][3],     ph[1], pl[1]);
            split2(s[2 * ks + 1][0], s[2 * ks + 1][1], ph[2], pl[2]);
            split2(s[2 * ks + 1][2], s[2 * ks + 1][3], ph[3], pl[3]);
            uint32_t vh[4][4], vl[4][4];
            #pragma unroll
            for (int hg = 0; hg < 4; ++hg) {
                const uint32_t voff = ((ks * 16 + l15) * FSTR + hg * 16 + l16 * 8) * 2;
                ldsm4t(vh[hg], vh_b + voff);
                ldsm4t(vl[hg], vl_b + voff);
            }
            // pass 1: Ph x Vh
            #pragma unroll
            for (int hg = 0; hg < 4; ++hg) {
                mma16816(o[2 * hg],     ph, vh[hg][0], vh[hg][1]);
                mma16816(o[2 * hg + 1], ph, vh[hg][2], vh[hg][3]);
            }
            // pass 2: Ph x Vl
            #pragma unroll
            for (int hg = 0; hg < 4; ++hg) {
                mma16816(o[2 * hg],     ph, vl[hg][0], vl[hg][1]);
                mma16816(o[2 * hg + 1], ph, vl[hg][2], vl[hg][3]);
            }
            // pass 3: Pl x Vh
            #pragma unroll
            for (int hg = 0; hg < 4; ++hg) {
                mma16816(o[2 * hg],     pl, vh[hg][0], vh[hg][1]);
                mma16816(o[2 * hg + 1], pl, vh[hg][2], vh[hg][3]);
            }
        }
        __syncthreads();
    }

    // ---- epilogue: y = O / l, split to gY hi/lo ----
    const float i0 = 1.0f / l0, i1 = 1.0f / l1;
    const int t0 = qb * BR + w * 16 + gid;
    #pragma unroll
    for (int nf = 0; nf < 8; ++nf) {
        const int col = h * 64 + nf * 8 + 2 * tig;
        uint32_t hi, lo;
        split2(o[nf][0] * i0, o[nf][1] * i0, hi, lo);
        *(uint32_t*)&gY_hi[t0][col] = hi;
        *(uint32_t*)&gY_lo[t0][col] = lo;
        split2(o[nf][2] * i1, o[nf][3] * i1, hi, lo);
        *(uint32_t*)&gY_hi[t0 + 8][col] = hi;
        *(uint32_t*)&gY_lo[t0 + 8][col] = lo;
    }
}

// ---------------- launch ---------------------------------------------------
extern "C" void kernel_launch(void* const* d_in, const int* in_sizes, int n_in,
                              void* d_out, int out_size)
{
    (void)in_sizes; (void)n_in; (void)out_size;
    const float* x     = (const float*)d_in[0];
    const float* Wqkv  = (const float*)d_in[1];
    const float* Wproj = (const float*)d_in[2];
    float* out = (float*)d_out;

    cudaFuncSetAttribute(mma_gemm_kernel<0>, cudaFuncAttributeMaxDynamicSharedMemorySize,
                         GEMM_SMEM);
    cudaFuncSetAttribute(mma_gemm_kernel<1>, cudaFuncAttributeMaxDynamicSharedMemorySize,
                         GEMM_SMEM);
    cudaFuncSetAttribute(flash_mma_kernel, cudaFuncAttributeMaxDynamicSharedMemorySize,
                         FLASH_SMEM_B);

    conv_split_kernel<<<SEQ_T * DIM / 4 / 256, 256>>>(x);
    transpose_split_kernel<0><<<dim3(3 * DIM / 32, DIM / 32), dim3(32, 8)>>>(Wqkv);
    transpose_split_kernel<1><<<dim3(DIM / 32, DIM / 32), dim3(32, 8)>>>(Wproj);

    // QKV = x @ W_qkv, split-scattered into gQ/gK/gV
    mma_gemm_kernel<0><<<dim3(3 * DIM / 128, SEQ_T / 128), 256, GEMM_SMEM>>>(
        nullptr, 3 * DIM);

    // fused attention -> gY hi/lo
    flash_mma_kernel<<<dim3(SEQ_T / BR, NUM_H), 256, FLASH_SMEM_B>>>();

    // out = y @ W_proj
    mma_gemm_kernel<1><<<dim3(DIM / 128, SEQ_T / 128), 256, GEMM_SMEM>>>(
        out, DIM);
}